// round 5
// baseline (speedup 1.0000x reference)
#include <cuda_runtime.h>
#include <math.h>

// Problem constants
#define BB   8
#define HW   14400   // 120*120
#define WATT 120
#define NP   10
#define PH   100
#define PW   100
#define CC   3
#define HH   1024
#define WHI  1024

#define CH    30       // chunks per batch
#define CHUNK 480      // elements per chunk (32 lanes x 15)
#define NC    (CH*NP)  // 300 candidates per batch

// d_out layout (flattened return tuple, all f32):
//   [0, 2400000)            patches (B,N,100,100,3)
//   [2400000, 2400080)      sampled_attention (B,N)
//   [2400080, 2400240)      offsets (B,N,2)
//   [2400240, 2400400)      samples (B,N,2) as float
#define PATCH_ELEMS (BB*NP*PH*PW*CC)   // 2,400,000
#define ROW_VEC     75                 // 300 floats per patch row = 75 float4
#define TOTAL_VEC   (PATCH_ELEMS/4)    // 600,000
#define GSTRIDE     (TOTAL_VEC/4)      // 150,000 (unroll factor 4)

#define FULL 0xffffffffu

__device__ int   g_corners[BB * NP * 2];
__device__ float g_cval[BB * NC];
__device__ int   g_cidx[BB * NC];

// ---------------------------------------------------------------------------
// Kernel A: per-warp chunk scores (registers) + top-10 via value-only
// butterfly max + equality-based index recovery. No smem, no index in chain.
// ---------------------------------------------------------------------------
__global__ void __launch_bounds__(128, 1)
score_topk_kernel(const float* __restrict__ att,
                  const float* __restrict__ u)
{
    const int wg   = (blockIdx.x * blockDim.x + threadIdx.x) >> 5;
    const int lane = threadIdx.x & 31;
    if (wg >= BB * CH) return;   // warp-uniform

    const int b    = wg / CH;
    const int ch   = wg % CH;
    const int base = ch * CHUNK;

    const float* a  = att + b * HW;
    const float* uu = u   + b * HW;

    // scores: log(max(att,1e-20)) - log(-log(clip(u,1e-6,1-1e-6)))
    float lv[16];
    #pragma unroll
    for (int j = 0; j < 15; j++) {
        int i = base + j * 32 + lane;
        float uv = fminf(fmaxf(uu[i], 1e-6f), 1.0f - 1e-6f);
        lv[j] = logf(fmaxf(a[i], 1e-20f)) - logf(-logf(uv));
    }
    lv[15] = -INFINITY;

    #pragma unroll 1
    for (int k = 0; k < NP; k++) {
        // lane max: pairwise fmaxf tree, depth 4, no index tracking
        float t8[8], t4[4], t2[2];
        #pragma unroll
        for (int j = 0; j < 8; j++) t8[j] = fmaxf(lv[2*j], lv[2*j+1]);
        #pragma unroll
        for (int j = 0; j < 4; j++) t4[j] = fmaxf(t8[2*j], t8[2*j+1]);
        t2[0] = fmaxf(t4[0], t4[1]);
        t2[1] = fmaxf(t4[2], t4[3]);
        float wmax = fmaxf(t2[0], t2[1]);

        // warp max: 5 butterfly steps, value only, all lanes get result
        #pragma unroll
        for (int s = 16; s > 0; s >>= 1)
            wmax = fmaxf(wmax, __shfl_xor_sync(FULL, wmax, s));

        // recover owner lane + slot by equality (ties measure-zero)
        unsigned bits = 0;
        #pragma unroll
        for (int j = 0; j < 15; j++)
            if (lv[j] == wmax) bits |= (1u << j);
        unsigned m = __ballot_sync(FULL, bits != 0);
        int owner = __ffs(m) - 1;
        int slot  = __ffs(bits) - 1;              // valid on owner
        slot = __shfl_sync(FULL, slot, owner);

        if (lane == 0) {
            g_cval[(b * CH + ch) * NP + k] = wmax;
            g_cidx[(b * CH + ch) * NP + k] = base + slot * 32 + owner;
        }

        // poison winner (constant-index predicated writes)
        bool own = (lane == owner);
        #pragma unroll
        for (int j = 0; j < 15; j++)
            if (own && j == slot) lv[j] = -INFINITY;
    }
}

// ---------------------------------------------------------------------------
// Kernel B: merge 300 candidates per batch -> global top-10. grid=B, 1 warp.
// Same value-only machinery.
// ---------------------------------------------------------------------------
__global__ void __launch_bounds__(32, 1)
merge_topk_kernel(const float* __restrict__ att,
                  float* __restrict__ out)
{
    const int b    = blockIdx.x;
    const int lane = threadIdx.x;

    float cv[10]; int ci[10];
    #pragma unroll
    for (int j = 0; j < 10; j++) {
        int c = j * 32 + lane;
        if (c < NC) { cv[j] = g_cval[b * NC + c]; ci[j] = g_cidx[b * NC + c]; }
        else        { cv[j] = -INFINITY;          ci[j] = 0; }
    }

    float* o_att  = out + PATCH_ELEMS;
    float* o_off  = o_att + BB * NP;
    float* o_samp = o_off + BB * NP * 2;

    #pragma unroll 1
    for (int k = 0; k < NP; k++) {
        // lane max tree over 10 (pad to 16 behavior via pairs)
        float p0 = fmaxf(cv[0], cv[1]);
        float p1 = fmaxf(cv[2], cv[3]);
        float p2 = fmaxf(cv[4], cv[5]);
        float p3 = fmaxf(cv[6], cv[7]);
        float p4 = fmaxf(cv[8], cv[9]);
        float q0 = fmaxf(p0, p1);
        float q1 = fmaxf(p2, p3);
        float wmax = fmaxf(fmaxf(q0, q1), p4);

        #pragma unroll
        for (int s = 16; s > 0; s >>= 1)
            wmax = fmaxf(wmax, __shfl_xor_sync(FULL, wmax, s));

        unsigned bits = 0;
        #pragma unroll
        for (int j = 0; j < 10; j++)
            if (cv[j] == wmax) bits |= (1u << j);
        unsigned m = __ballot_sync(FULL, bits != 0);
        int owner = __ffs(m) - 1;
        int slot  = __ffs(bits) - 1;

        // owner extracts its candidate's global index, broadcast it
        int gi = 0;
        #pragma unroll
        for (int j = 0; j < 10; j++)
            if (j == slot) gi = ci[j];
        gi = __shfl_sync(FULL, gi, owner);

        if (lane == 0) {
            int wi = gi;
            int iy = wi / WATT;
            int ix = wi % WATT;

            o_att[b * NP + k] = att[b * HW + wi];
            // offsets = (sample + RF/2) * scale = (s+4)*8 exactly
            o_off[(b * NP + k) * 2 + 0] = (float)((iy + 4) * 8);
            o_off[(b * NP + k) * 2 + 1] = (float)((ix + 4) * 8);
            o_samp[(b * NP + k) * 2 + 0] = (float)iy;
            o_samp[(b * NP + k) * 2 + 1] = (float)ix;

            int cy = (iy + 4) * 8; if (cy > HH  - PH) cy = HH  - PH;
            int cx = (ix + 4) * 8; if (cx > WHI - PW) cx = WHI - PW;
            g_corners[(b * NP + k) * 2 + 0] = cy;
            g_corners[(b * NP + k) * 2 + 1] = cx;
        }

        // poison
        bool own = (lane == owner);
        slot = __shfl_sync(FULL, slot, owner);   // ensure defined on all lanes
        #pragma unroll
        for (int j = 0; j < 10; j++)
            if (own && j == slot) cv[j] = -INFINITY;
    }
}

// ---------------------------------------------------------------------------
// Kernel C: patch gather, 4 independent float4s per thread (MLP=4)
// ---------------------------------------------------------------------------
__global__ void __launch_bounds__(256)
gather_kernel(const float* __restrict__ xh,
              float* __restrict__ out)
{
    int t = blockIdx.x * blockDim.x + threadIdx.x;
    if (t >= GSTRIDE) return;

    #pragma unroll
    for (int r = 0; r < 4; r++) {
        int v = t + r * GSTRIDE;

        int col = v % ROW_VEC;
        int row = v / ROW_VEC;
        int y   = row % PH;
        int pn  = row / PH;              // b*NP + n

        int cy = g_corners[pn * 2 + 0];
        int cx = g_corners[pn * 2 + 1];
        int b  = pn / NP;

        const float4* src = reinterpret_cast<const float4*>(
            xh + ((size_t)(b * HH + cy + y) * WHI + cx) * CC);
        reinterpret_cast<float4*>(out)[v] = src[col];
    }
}

// ---------------------------------------------------------------------------
extern "C" void kernel_launch(void* const* d_in, const int* in_sizes, int n_in,
                              void* d_out, int out_size)
{
    // metadata order: x_low, x_high, attention, uniform_noise
    const float* x_high = (const float*)d_in[1];
    const float* att    = (const float*)d_in[2];
    const float* unoise = (const float*)d_in[3];
    float* out = (float*)d_out;

    // Kernel A: 240 warps, 4 warps/block -> 60 blocks
    score_topk_kernel<<<60, 128>>>(att, unoise);
    // Kernel B: one warp per batch
    merge_topk_kernel<<<BB, 32>>>(att, out);
    // Kernel C: gather
    const int threads = 256;
    const int blocks  = (GSTRIDE + threads - 1) / threads;
    gather_kernel<<<blocks, threads>>>(x_high, out);
}

// round 6
// speedup vs baseline: 1.1530x; 1.1530x over previous
#include <cuda_runtime.h>
#include <math.h>

// Problem constants
#define BB   8
#define HW   14400   // 120*120
#define WATT 120
#define NP   10
#define PH   100
#define PW   100
#define CC   3
#define HH   1024
#define WHI  1024

#define CH    30       // chunks per batch
#define CHUNK 480      // elements per chunk (32 lanes x 15)
#define NC    (CH*NP)  // 300 candidates per batch

// d_out layout (flattened return tuple, all f32):
//   [0, 2400000)            patches (B,N,100,100,3)
//   [2400000, 2400080)      sampled_attention (B,N)
//   [2400080, 2400240)      offsets (B,N,2)
//   [2400240, 2400400)      samples (B,N,2) as float
#define PATCH_ELEMS (BB*NP*PH*PW*CC)   // 2,400,000
#define ROW_VEC     75                 // 300 floats per patch row = 75 float4
#define TOTAL_VEC   (PATCH_ELEMS/4)    // 600,000
#define GUNROLL     8
#define GSTRIDE     (TOTAL_VEC/GUNROLL)  // 75,000

#define FULL 0xffffffffu

__device__ int      g_corners[BB * NP * 2];
__device__ unsigned g_ckey[BB * NC];
__device__ int      g_cidx[BB * NC];

// order-preserving float->u32 key: all real floats map monotonically;
// poison value 0u is below every real key (-inf -> 0x007FFFFF).
__device__ __forceinline__ unsigned f2key(float f) {
    unsigned x = __float_as_uint(f);
    return x ^ ((unsigned)(((int)x) >> 31) | 0x80000000u);
}

// ---------------------------------------------------------------------------
// Kernel A: per-warp chunk scores -> u32 keys in registers; top-10 via
// IMNMX tree + single REDUX.SYNC.MAX per pass. No smem, no barriers.
// ---------------------------------------------------------------------------
__global__ void __launch_bounds__(128, 1)
score_topk_kernel(const float* __restrict__ att,
                  const float* __restrict__ u)
{
    const int wg   = (blockIdx.x * blockDim.x + threadIdx.x) >> 5;
    const int lane = threadIdx.x & 31;
    if (wg >= BB * CH) return;   // warp-uniform

    const int b    = wg / CH;
    const int ch   = wg % CH;
    const int base = ch * CHUNK;

    const float* a  = att + b * HW;
    const float* uu = u   + b * HW;

    // scores: log(max(att,1e-20)) - log(-log(clip(u,1e-6,1-1e-6)))
    // __logf: ordering-only (order-statistic gaps >> 1e-5 error)
    unsigned lv[16];
    #pragma unroll
    for (int j = 0; j < 15; j++) {
        int i = base + j * 32 + lane;
        float uv = fminf(fmaxf(uu[i], 1e-6f), 1.0f - 1e-6f);
        float s  = __logf(fmaxf(a[i], 1e-20f)) - __logf(-__logf(uv));
        lv[j] = f2key(s);
    }
    lv[15] = 0u;

    #pragma unroll 1
    for (int k = 0; k < NP; k++) {
        // lane max: pairwise integer max tree (depth 4)
        unsigned t8[8], t4[4];
        #pragma unroll
        for (int j = 0; j < 8; j++) t8[j] = max(lv[2*j], lv[2*j+1]);
        #pragma unroll
        for (int j = 0; j < 4; j++) t4[j] = max(t8[2*j], t8[2*j+1]);
        unsigned wmax = max(max(t4[0], t4[1]), max(t4[2], t4[3]));

        // ONE hardware warp reduction
        wmax = __reduce_max_sync(FULL, wmax);

        // recover owner lane + slot by exact integer equality
        unsigned bits = 0;
        #pragma unroll
        for (int j = 0; j < 15; j++)
            if (lv[j] == wmax) bits |= (1u << j);
        unsigned m = __ballot_sync(FULL, bits != 0);
        int owner = __ffs(m) - 1;
        int slot  = __ffs(bits) - 1;              // valid on owner
        int gidx  = __shfl_sync(FULL, base + slot * 32 + lane, owner);

        if (lane == 0) {
            g_ckey[(b * CH + ch) * NP + k] = wmax;
            g_cidx[(b * CH + ch) * NP + k] = gidx;
        }

        // poison winner
        bool own = (lane == owner);
        slot = __shfl_sync(FULL, slot, owner);
        #pragma unroll
        for (int j = 0; j < 15; j++)
            if (own && j == slot) lv[j] = 0u;
    }
}

// ---------------------------------------------------------------------------
// Kernel B: merge 300 candidates per batch -> global top-10. grid=B, 1 warp.
// ---------------------------------------------------------------------------
__global__ void __launch_bounds__(32, 1)
merge_topk_kernel(const float* __restrict__ att,
                  float* __restrict__ out)
{
    const int b    = blockIdx.x;
    const int lane = threadIdx.x;

    unsigned cv[10]; int ci[10];
    #pragma unroll
    for (int j = 0; j < 10; j++) {
        int c = j * 32 + lane;
        if (c < NC) { cv[j] = g_ckey[b * NC + c]; ci[j] = g_cidx[b * NC + c]; }
        else        { cv[j] = 0u;                 ci[j] = 0; }
    }

    float* o_att  = out + PATCH_ELEMS;
    float* o_off  = o_att + BB * NP;
    float* o_samp = o_off + BB * NP * 2;

    #pragma unroll 1
    for (int k = 0; k < NP; k++) {
        unsigned p0 = max(cv[0], cv[1]);
        unsigned p1 = max(cv[2], cv[3]);
        unsigned p2 = max(cv[4], cv[5]);
        unsigned p3 = max(cv[6], cv[7]);
        unsigned p4 = max(cv[8], cv[9]);
        unsigned wmax = max(max(max(p0, p1), max(p2, p3)), p4);

        wmax = __reduce_max_sync(FULL, wmax);

        unsigned bits = 0;
        #pragma unroll
        for (int j = 0; j < 10; j++)
            if (cv[j] == wmax) bits |= (1u << j);
        unsigned m = __ballot_sync(FULL, bits != 0);
        int owner = __ffs(m) - 1;
        int slot  = __ffs(bits) - 1;

        int gi = 0;
        #pragma unroll
        for (int j = 0; j < 10; j++)
            if (j == slot) gi = ci[j];
        gi = __shfl_sync(FULL, gi, owner);

        if (lane == 0) {
            int wi = gi;
            int iy = wi / WATT;
            int ix = wi % WATT;

            o_att[b * NP + k] = att[b * HW + wi];
            // offsets = (sample + RF/2) * scale = (s+4)*8 exactly
            o_off[(b * NP + k) * 2 + 0] = (float)((iy + 4) * 8);
            o_off[(b * NP + k) * 2 + 1] = (float)((ix + 4) * 8);
            o_samp[(b * NP + k) * 2 + 0] = (float)iy;
            o_samp[(b * NP + k) * 2 + 1] = (float)ix;

            int cy = (iy + 4) * 8; if (cy > HH  - PH) cy = HH  - PH;
            int cx = (ix + 4) * 8; if (cx > WHI - PW) cx = WHI - PW;
            g_corners[(b * NP + k) * 2 + 0] = cy;
            g_corners[(b * NP + k) * 2 + 1] = cx;
        }

        // poison
        bool own = (lane == owner);
        slot = __shfl_sync(FULL, slot, owner);
        #pragma unroll
        for (int j = 0; j < 10; j++)
            if (own && j == slot) cv[j] = 0u;
    }
}

// ---------------------------------------------------------------------------
// Kernel C: patch gather, 8 independent float4s per thread (MLP=8)
// ---------------------------------------------------------------------------
__global__ void __launch_bounds__(256)
gather_kernel(const float* __restrict__ xh,
              float* __restrict__ out)
{
    int t = blockIdx.x * blockDim.x + threadIdx.x;
    if (t >= GSTRIDE) return;

    #pragma unroll
    for (int r = 0; r < GUNROLL; r++) {
        int v = t + r * GSTRIDE;

        int col = v % ROW_VEC;
        int row = v / ROW_VEC;
        int y   = row % PH;
        int pn  = row / PH;              // b*NP + n

        int cy = g_corners[pn * 2 + 0];
        int cx = g_corners[pn * 2 + 1];
        int b  = pn / NP;

        const float4* src = reinterpret_cast<const float4*>(
            xh + ((size_t)(b * HH + cy + y) * WHI + cx) * CC);
        reinterpret_cast<float4*>(out)[v] = src[col];
    }
}

// ---------------------------------------------------------------------------
extern "C" void kernel_launch(void* const* d_in, const int* in_sizes, int n_in,
                              void* d_out, int out_size)
{
    // metadata order: x_low, x_high, attention, uniform_noise
    const float* x_high = (const float*)d_in[1];
    const float* att    = (const float*)d_in[2];
    const float* unoise = (const float*)d_in[3];
    float* out = (float*)d_out;

    // Kernel A: 240 warps, 4 warps/block -> 60 blocks
    score_topk_kernel<<<60, 128>>>(att, unoise);
    // Kernel B: one warp per batch
    merge_topk_kernel<<<BB, 32>>>(att, out);
    // Kernel C: gather
    const int threads = 256;
    const int blocks  = (GSTRIDE + threads - 1) / threads;
    gather_kernel<<<blocks, threads>>>(x_high, out);
}